// round 7
// baseline (speedup 1.0000x reference)
#include <cuda_runtime.h>
#include <math.h>

#define B_NO   8
#define T_LEN  10000
#define E_NUM  1000
#define I_NUM  250
#define SUB_NO 8
#define HID_NO 16
#define CBAS   30
#define T_NO   200

// output layout: final | sub_out | C_syn_e | C_syn_i
#define FINAL_OFF  0
#define SUBOUT_OFF (B_NO * T_LEN)                       // 80000
#define CE_OFF     (SUBOUT_OFF + B_NO * T_LEN * SUB_NO) // 720000
#define CI_OFF     (CE_OFF + SUB_NO * E_NUM)            // 728000

// ---------------- device scratch ----------------
__device__ __align__(16) float g_kern_e[SUB_NO * T_NO * HID_NO];  // [s][tau][h]
__device__ __align__(16) float g_kern_i[SUB_NO * T_NO * HID_NO];
__device__ float g_syn_e[B_NO * SUB_NO * T_LEN];                  // [b][s][t]
__device__ float g_syn_i[B_NO * SUB_NO * T_LEN];
// transposed+swizzled scaled C matrices
// E: 256 e4-rows x 8 float4 (float4 j = (ee*2+half)^(e4&7); holds s=4*half..4*half+3 at e=e4*4+ee)
__device__ float4 g_CeT[256 * 8];
// I: [e][10] floats (s contiguous), e < 256, zero padded
__device__ float4 g_CiT4[640];   // 2560 floats

// ---------------- helpers ----------------
__device__ __forceinline__ float2 ffma2(float2 a, float2 b, float2 c) {
    union U { float2 f; unsigned long long u; };
    U A, B, C, D;
    A.f = a; B.f = b; C.f = c;
    asm("fma.rn.f32x2 %0, %1, %2, %3;" : "=l"(D.u) : "l"(A.u), "l"(B.u), "l"(C.u));
    return D.f;
}

__device__ __forceinline__ float tanh_fast(float x) {
    float e = __expf(2.0f * x);
    return 1.0f - __fdividef(2.0f, e + 1.0f);
}

__device__ __forceinline__ float2 shfl_xor_f2(float2 v, int m) {
    union { float2 f; double d; } u;
    u.f = v;
    u.d = __shfl_xor_sync(0xffffffffu, u.d, m);
    return u.f;
}

// ---------------- K-1: zero the transposed C scratch ----------------
__global__ void init_ct_kernel() {
    int idx = blockIdx.x * blockDim.x + threadIdx.x;
    float4 z = make_float4(0.f, 0.f, 0.f, 0.f);
    if (idx < 2048) g_CeT[idx] = z;
    if (idx < 640)  g_CiT4[idx] = z;
}

// ---------------- K0: softmax + scaled transposed copies ----------------
__global__ void softmax_kernel(const float* __restrict__ Cer,
                               const float* __restrict__ Cir,
                               const float* __restrict__ Es,
                               const float* __restrict__ Is,
                               float* __restrict__ out) {
    int idx = blockIdx.x * blockDim.x + threadIdx.x;
    if (idx < E_NUM) {
        float u[SUB_NO], p[SUB_NO], sc_v[SUB_NO];
        float m = -1e30f;
#pragma unroll
        for (int s = 0; s < SUB_NO; ++s) { u[s] = Cer[s * E_NUM + idx] * 10000.0f; m = fmaxf(m, u[s]); }
        float sum = 0.0f;
#pragma unroll
        for (int s = 0; s < SUB_NO; ++s) { p[s] = expf(u[s] - m); sum += p[s]; }
        float inv = 1.0f / sum;
        float sc  = expf(Es[idx]);
#pragma unroll
        for (int s = 0; s < SUB_NO; ++s) {
            float v = p[s] * inv;
            out[CE_OFF + s * E_NUM + idx] = v;
            sc_v[s] = v * sc;
        }
        int e4 = idx >> 2, ee = idx & 3, swz = e4 & 7;
#pragma unroll
        for (int half = 0; half < 2; ++half) {
            int phys = e4 * 8 + ((ee * 2 + half) ^ swz);
            g_CeT[phys] = make_float4(sc_v[half * 4 + 0], sc_v[half * 4 + 1],
                                      sc_v[half * 4 + 2], sc_v[half * 4 + 3]);
        }
    } else if (idx < E_NUM + I_NUM) {
        int j = idx - E_NUM;
        float u[SUB_NO], p[SUB_NO];
        float m = -1e30f;
#pragma unroll
        for (int s = 0; s < SUB_NO; ++s) { u[s] = Cir[s * I_NUM + j] * 10000.0f; m = fmaxf(m, u[s]); }
        float sum = 0.0f;
#pragma unroll
        for (int s = 0; s < SUB_NO; ++s) { p[s] = expf(u[s] - m); sum += p[s]; }
        float inv = 1.0f / sum;
        float sc  = expf(Is[j]);
        float* ct = (float*)g_CiT4;
#pragma unroll
        for (int s = 0; s < SUB_NO; ++s) {
            float v = p[s] * inv;
            out[CI_OFF + s * I_NUM + j] = v;
            ct[j * 10 + s] = v * sc;
        }
    }
}

// ---------------- K1: temporal kernels from cosine basis ----------------
__global__ void kern_kernel(const float* __restrict__ W_e,
                            const float* __restrict__ W_i) {
    __shared__ float bas[CBAS];
    int tau = blockIdx.x;
    if (threadIdx.x < CBAS) {
        double phi = 0.5 * M_PI * (double)threadIdx.x;
        double raw = 7.5 * log((double)tau + 1.0 + 1e-7);
        double v = 0.0;
        if (raw >= phi - M_PI && raw <= phi + M_PI)
            v = 0.5 * cos(raw - phi) + 0.5;
        bas[threadIdx.x] = (float)v;
    }
    __syncthreads();
    int r = threadIdx.x;             // 0..127
    float ae = 0.0f, ai = 0.0f;
#pragma unroll
    for (int c = 0; c < CBAS; ++c) {
        ae = fmaf(W_e[r * CBAS + c], bas[c], ae);
        ai = fmaf(W_i[r * CBAS + c], bas[c], ai);
    }
    int s = r >> 4, h = r & 15;
    g_kern_e[(s * T_NO + tau) * HID_NO + h] = ae;
    g_kern_i[(s * T_NO + tau) * HID_NO + h] = ai;
}

// ---------------- K2: synapse pooling (HBM-bound) ----------------
#define POOL_GX  74
#define N_TILES  313          // ceil(10000/32)

__device__ __forceinline__ void loadE4(const float* __restrict__ S_e, size_t rowE0,
                                       int t0, int e, float4 (&v)[4]) {
#pragma unroll
    for (int r = 0; r < 4; ++r) {
        int t = t0 + r;
        v[r] = (t < T_LEN && e < E_NUM)
                ? __ldg((const float4*)(S_e + (rowE0 + t) * E_NUM + e))
                : make_float4(0.f, 0.f, 0.f, 0.f);
    }
}

__device__ __forceinline__ void loadI2(const float* __restrict__ S_i, size_t rowE0,
                                       int t0, int p, float2 (&v)[4]) {
#pragma unroll
    for (int r = 0; r < 4; ++r) {
        int t = t0 + r;
        v[r] = (t < T_LEN && p < 125)
                ? __ldg((const float2*)(S_i + (rowE0 + t) * I_NUM + p * 2))
                : make_float2(0.f, 0.f);
    }
}

__global__ void __launch_bounds__(256)
pool_kernel(const float* __restrict__ S_e, const float* __restrict__ S_i) {
    __shared__ float4 shCe[256 * 8];   // 32KB, swizzled layout as g_CeT
    __shared__ float  shCi[2560];      // 10KB, [e][10]

    int tid = threadIdx.x;
    for (int i = tid; i < 2048; i += 256) shCe[i] = g_CeT[i];
    for (int i = tid; i < 640; i += 256) ((float4*)shCi)[i] = g_CiT4[i];
    __syncthreads();

    int b = blockIdx.y;
    int warp = tid >> 5, lane = tid & 31;
    size_t rowE0 = (size_t)b * T_LEN;
    float* dstE = &g_syn_e[b * SUB_NO * T_LEN];
    float* dstI = &g_syn_i[b * SUB_NO * T_LEN];

    for (int tile = blockIdx.x; tile < N_TILES; tile += POOL_GX) {
        int t0 = tile * 32 + warp * 4;

        float2 acc[4][4];
#pragma unroll
        for (int r = 0; r < 4; ++r)
#pragma unroll
            for (int sp = 0; sp < 4; ++sp) acc[r][sp] = make_float2(0.f, 0.f);

        // ---- excitatory: 8 chunks of 128 e, software-pipelined ----
        float4 cur[4], nxt[4];
        loadE4(S_e, rowE0, t0, lane * 4, cur);
#pragma unroll 2
        for (int chunk = 0; chunk < 8; ++chunk) {
            if (chunk < 7)
                loadE4(S_e, rowE0, t0, (chunk + 1) * 128 + lane * 4, nxt);
            int e4 = chunk * 32 + lane;
            int swz = e4 & 7;
            const float4* she = &shCe[e4 * 8];
#pragma unroll
            for (int ee = 0; ee < 4; ++ee) {
                float4 cA = she[(ee * 2 + 0) ^ swz];
                float4 cB = she[(ee * 2 + 1) ^ swz];
                float2 c0 = make_float2(cA.x, cA.y), c1 = make_float2(cA.z, cA.w);
                float2 c2 = make_float2(cB.x, cB.y), c3 = make_float2(cB.z, cB.w);
#pragma unroll
                for (int r = 0; r < 4; ++r) {
                    float x = (ee == 0) ? cur[r].x : (ee == 1) ? cur[r].y
                             : (ee == 2) ? cur[r].z : cur[r].w;
                    float2 vv = make_float2(x, x);
                    acc[r][0] = ffma2(c0, vv, acc[r][0]);
                    acc[r][1] = ffma2(c1, vv, acc[r][1]);
                    acc[r][2] = ffma2(c2, vv, acc[r][2]);
                    acc[r][3] = ffma2(c3, vv, acc[r][3]);
                }
            }
#pragma unroll
            for (int r = 0; r < 4; ++r) cur[r] = nxt[r];
        }
        // reduce + write E
        {
#pragma unroll
            for (int st = 16; st >= 1; st >>= 1)
#pragma unroll
                for (int r = 0; r < 4; ++r)
#pragma unroll
                    for (int sp = 0; sp < 4; ++sp) {
                        float2 o = shfl_xor_f2(acc[r][sp], st);
                        acc[r][sp].x += o.x; acc[r][sp].y += o.y;
                    }
            int i = lane >> 3, s = lane & 7;
            int t = t0 + i;
            if (t < T_LEN) {
                float2 v2 = acc[i][s >> 1];
                dstE[s * T_LEN + t] = (s & 1) ? v2.y : v2.x;
            }
        }

        // ---- inhibitory: 4 chunks of 32 float2, pipelined ----
#pragma unroll
        for (int r = 0; r < 4; ++r)
#pragma unroll
            for (int sp = 0; sp < 4; ++sp) acc[r][sp] = make_float2(0.f, 0.f);

        float2 curI[4], nxtI[4];
        loadI2(S_i, rowE0, t0, lane, curI);
#pragma unroll 2
        for (int chunk = 0; chunk < 4; ++chunk) {
            if (chunk < 3)
                loadI2(S_i, rowE0, t0, (chunk + 1) * 32 + lane, nxtI);
            int p = chunk * 32 + lane;
#pragma unroll
            for (int ee = 0; ee < 2; ++ee) {
                int e = p * 2 + ee;
                const float* ci = &shCi[e * 10];
                float2 c0 = *(const float2*)(ci + 0);
                float2 c1 = *(const float2*)(ci + 2);
                float2 c2 = *(const float2*)(ci + 4);
                float2 c3 = *(const float2*)(ci + 6);
#pragma unroll
                for (int r = 0; r < 4; ++r) {
                    float x = ee ? curI[r].y : curI[r].x;
                    float2 vv = make_float2(x, x);
                    acc[r][0] = ffma2(c0, vv, acc[r][0]);
                    acc[r][1] = ffma2(c1, vv, acc[r][1]);
                    acc[r][2] = ffma2(c2, vv, acc[r][2]);
                    acc[r][3] = ffma2(c3, vv, acc[r][3]);
                }
            }
#pragma unroll
            for (int r = 0; r < 4; ++r) curI[r] = nxtI[r];
        }
        // reduce + write I
        {
#pragma unroll
            for (int st = 16; st >= 1; st >>= 1)
#pragma unroll
                for (int r = 0; r < 4; ++r)
#pragma unroll
                    for (int sp = 0; sp < 4; ++sp) {
                        float2 o = shfl_xor_f2(acc[r][sp], st);
                        acc[r][sp].x += o.x; acc[r][sp].y += o.y;
                    }
            int i = lane >> 3, s = lane & 7;
            int t = t0 + i;
            if (t < T_LEN) {
                float2 v2 = acc[i][s >> 1];
                dstI[s * T_LEN + t] = (s & 1) ? v2.y : v2.x;
            }
        }
    }
}

// ---------------- K3: causal conv + tanh + readout (fma-bound) ----------------
#define CROWS 3
#define TC (256 * CROWS)      // 768
#define XW (TC + T_NO)        // 968

__global__ void __launch_bounds__(256)
conv_kernel(const float* __restrict__ W2,
            const float* __restrict__ b1,
            float* __restrict__ out) {
    __shared__ __align__(16) float4 sKe[T_NO * 4];   // [tau][4 float4] = 16 h
    __shared__ __align__(16) float4 sKi[T_NO * 4];
    __shared__ float sXe[XW], sXi[XW];
    __shared__ float sEw2[HID_NO], sB1[HID_NO];

    int tid = threadIdx.x;
    int bs = blockIdx.y;
    int b = bs >> 3, s = bs & 7;
    int t0 = blockIdx.x * TC;

    const float4* ge = (const float4*)g_kern_e + s * (T_NO * 4);
    const float4* gi = (const float4*)g_kern_i + s * (T_NO * 4);
    for (int idx = tid; idx < T_NO * 4; idx += 256) {
        sKe[idx] = ge[idx];
        sKi[idx] = gi[idx];
    }
    for (int idx = tid; idx < XW; idx += 256) {
        int g = t0 - (T_NO - 1) + idx;
        bool ok = (g >= 0) && (g < T_LEN);
        sXe[idx] = ok ? g_syn_e[(b * SUB_NO + s) * T_LEN + g] : 0.0f;
        sXi[idx] = ok ? g_syn_i[(b * SUB_NO + s) * T_LEN + g] : 0.0f;
    }
    if (tid < HID_NO) {
        sEw2[tid] = expf(W2[s * HID_NO + tid]);
        sB1[tid]  = b1[s * HID_NO + tid];
    }
    __syncthreads();

    float2 acc[CROWS][8];
#pragma unroll
    for (int r = 0; r < CROWS; ++r)
#pragma unroll
        for (int hp = 0; hp < 8; ++hp) acc[r][hp] = make_float2(0.f, 0.f);

    int o0 = tid + (T_NO - 1);

#pragma unroll 2
    for (int tau = 0; tau < T_NO; ++tau) {
        float4 ke[4], ki[4];
#pragma unroll
        for (int q = 0; q < 4; ++q) { ke[q] = sKe[tau * 4 + q]; ki[q] = sKi[tau * 4 + q]; }
        float xe[CROWS], xi[CROWS];
#pragma unroll
        for (int r = 0; r < CROWS; ++r) {
            xe[r] = sXe[o0 + r * 256 - tau];
            xi[r] = sXi[o0 + r * 256 - tau];
        }
#pragma unroll
        for (int r = 0; r < CROWS; ++r) {
            float2 ve = make_float2(xe[r], xe[r]);
            float2 vi = make_float2(xi[r], xi[r]);
#pragma unroll
            for (int q = 0; q < 4; ++q) {
                acc[r][2*q]   = ffma2(make_float2(ke[q].x, ke[q].y), ve, acc[r][2*q]);
                acc[r][2*q+1] = ffma2(make_float2(ke[q].z, ke[q].w), ve, acc[r][2*q+1]);
                acc[r][2*q]   = ffma2(make_float2(ki[q].x, ki[q].y), vi, acc[r][2*q]);
                acc[r][2*q+1] = ffma2(make_float2(ki[q].z, ki[q].w), vi, acc[r][2*q+1]);
            }
        }
    }

    // epilogue: tanh + positive readout -> sub_out[b, t, s]
#pragma unroll
    for (int r = 0; r < CROWS; ++r) {
        int t = t0 + tid + r * 256;
        if (t < T_LEN) {
            float so = 0.0f;
#pragma unroll
            for (int hp = 0; hp < 8; ++hp) {
                so = fmaf(sEw2[2*hp],   tanh_fast(acc[r][hp].x + sB1[2*hp]),   so);
                so = fmaf(sEw2[2*hp+1], tanh_fast(acc[r][hp].y + sB1[2*hp+1]), so);
            }
            out[SUBOUT_OFF + (size_t)(b * T_LEN + t) * SUB_NO + s] = so;
        }
    }
}

// ---------------- K4: final = sum_s sub_out + V_o ----------------
__global__ void final_kernel(const float* __restrict__ V_o, float* __restrict__ out) {
    int idx = blockIdx.x * blockDim.x + threadIdx.x;
    if (idx >= B_NO * T_LEN) return;
    const float4* p = (const float4*)&out[SUBOUT_OFF + (size_t)idx * SUB_NO];
    float4 a = p[0], c = p[1];
    out[FINAL_OFF + idx] = V_o[0] + ((a.x + a.y) + (a.z + a.w)) + ((c.x + c.y) + (c.z + c.w));
}

// ---------------- launch ----------------
extern "C" void kernel_launch(void* const* d_in, const int* in_sizes, int n_in,
                              void* d_out, int out_size) {
    (void)in_sizes; (void)n_in; (void)out_size;
    const float* S_e   = (const float*)d_in[0];
    const float* S_i   = (const float*)d_in[1];
    const float* Es    = (const float*)d_in[2];
    const float* Is    = (const float*)d_in[3];
    const float* W_e   = (const float*)d_in[4];
    const float* W_i   = (const float*)d_in[5];
    const float* W2    = (const float*)d_in[6];
    const float* b1    = (const float*)d_in[7];
    const float* Cer   = (const float*)d_in[8];
    const float* Cir   = (const float*)d_in[9];
    const float* V_o   = (const float*)d_in[10];
    float* out = (float*)d_out;

    init_ct_kernel<<<8, 256>>>();
    softmax_kernel<<<(E_NUM + I_NUM + 255) / 256, 256>>>(Cer, Cir, Es, Is, out);
    kern_kernel<<<T_NO, 128>>>(W_e, W_i);

    dim3 pg(POOL_GX, B_NO);                       // 74 x 8 = 592 blocks
    pool_kernel<<<pg, 256>>>(S_e, S_i);

    dim3 cg((T_LEN + TC - 1) / TC, B_NO * SUB_NO);  // 14 x 64
    conv_kernel<<<cg, 256>>>(W2, b1, out);

    final_kernel<<<(B_NO * T_LEN + 255) / 256, 256>>>(V_o, out);
}

// round 9
// speedup vs baseline: 1.3882x; 1.3882x over previous
#include <cuda_runtime.h>
#include <math.h>

#define B_NO   8
#define T_LEN  10000
#define E_NUM  1000
#define I_NUM  250
#define SUB_NO 8
#define HID_NO 16
#define CBAS   30
#define T_NO   200

// output layout: final | sub_out | C_syn_e | C_syn_i
#define FINAL_OFF  0
#define SUBOUT_OFF (B_NO * T_LEN)                       // 80000
#define CE_OFF     (SUBOUT_OFF + B_NO * T_LEN * SUB_NO) // 720000
#define CI_OFF     (CE_OFF + SUB_NO * E_NUM)            // 728000

// ---------------- device scratch ----------------
__device__ __align__(16) float g_kern_e[SUB_NO * T_NO * HID_NO];  // [s][tau][h]
__device__ __align__(16) float g_kern_i[SUB_NO * T_NO * HID_NO];
__device__ float g_syn_e[B_NO * SUB_NO * T_LEN];                  // [b][s][t]
__device__ float g_syn_i[B_NO * SUB_NO * T_LEN];
// scaled transposed C: [e][8] floats, e-padded (zeros beyond E_NUM/I_NUM)
__device__ __align__(16) float g_CTe[1024 * 8];
__device__ __align__(16) float g_CTi[256 * 8];

// ---------------- helpers ----------------
__device__ __forceinline__ float2 ffma2(float2 a, float2 b, float2 c) {
    union U { float2 f; unsigned long long u; };
    U A, B, C, D;
    A.f = a; B.f = b; C.f = c;
    asm("fma.rn.f32x2 %0, %1, %2, %3;" : "=l"(D.u) : "l"(A.u), "l"(B.u), "l"(C.u));
    return D.f;
}

__device__ __forceinline__ float tanh_fast(float x) {
    float e = __expf(2.0f * x);
    return 1.0f - __fdividef(2.0f, e + 1.0f);
}

// ---------------- K0: softmax + scaled transposed copies (+padding zero) ----------------
__global__ void softmax_kernel(const float* __restrict__ Cer,
                               const float* __restrict__ Cir,
                               const float* __restrict__ Es,
                               const float* __restrict__ Is,
                               float* __restrict__ out) {
    int idx = blockIdx.x * blockDim.x + threadIdx.x;
    if (idx < E_NUM) {
        float u[SUB_NO], p[SUB_NO];
        float m = -1e30f;
#pragma unroll
        for (int s = 0; s < SUB_NO; ++s) { u[s] = Cer[s * E_NUM + idx] * 10000.0f; m = fmaxf(m, u[s]); }
        float sum = 0.0f;
#pragma unroll
        for (int s = 0; s < SUB_NO; ++s) { p[s] = expf(u[s] - m); sum += p[s]; }
        float inv = 1.0f / sum;
        float sc  = expf(Es[idx]);
#pragma unroll
        for (int s = 0; s < SUB_NO; ++s) {
            float v = p[s] * inv;
            out[CE_OFF + s * E_NUM + idx] = v;
            g_CTe[idx * 8 + s] = v * sc;
        }
    } else if (idx < E_NUM + I_NUM) {
        int j = idx - E_NUM;
        float u[SUB_NO], p[SUB_NO];
        float m = -1e30f;
#pragma unroll
        for (int s = 0; s < SUB_NO; ++s) { u[s] = Cir[s * I_NUM + j] * 10000.0f; m = fmaxf(m, u[s]); }
        float sum = 0.0f;
#pragma unroll
        for (int s = 0; s < SUB_NO; ++s) { p[s] = expf(u[s] - m); sum += p[s]; }
        float inv = 1.0f / sum;
        float sc  = expf(Is[j]);
#pragma unroll
        for (int s = 0; s < SUB_NO; ++s) {
            float v = p[s] * inv;
            out[CI_OFF + s * I_NUM + j] = v;
            g_CTi[j * 8 + s] = v * sc;
        }
    } else if (idx < E_NUM + I_NUM + 24) {       // zero-pad C_e rows [1000,1024)
        int row = E_NUM + (idx - (E_NUM + I_NUM));
#pragma unroll
        for (int s = 0; s < SUB_NO; ++s) g_CTe[row * 8 + s] = 0.0f;
    } else if (idx < E_NUM + I_NUM + 24 + 6) {   // zero-pad C_i rows [250,256)
        int row = I_NUM + (idx - (E_NUM + I_NUM + 24));
#pragma unroll
        for (int s = 0; s < SUB_NO; ++s) g_CTi[row * 8 + s] = 0.0f;
    }
}

// ---------------- K1: temporal kernels from cosine basis ----------------
__global__ void kern_kernel(const float* __restrict__ W_e,
                            const float* __restrict__ W_i) {
    __shared__ float bas[CBAS];
    int tau = blockIdx.x;
    if (threadIdx.x < CBAS) {
        double phi = 0.5 * M_PI * (double)threadIdx.x;
        double raw = 7.5 * log((double)tau + 1.0 + 1e-7);
        double v = 0.0;
        if (raw >= phi - M_PI && raw <= phi + M_PI)
            v = 0.5 * cos(raw - phi) + 0.5;
        bas[threadIdx.x] = (float)v;
    }
    __syncthreads();
    int r = threadIdx.x;             // 0..127
    float ae = 0.0f, ai = 0.0f;
#pragma unroll
    for (int c = 0; c < CBAS; ++c) {
        ae = fmaf(W_e[r * CBAS + c], bas[c], ae);
        ai = fmaf(W_i[r * CBAS + c], bas[c], ai);
    }
    int s = r >> 4, h = r & 15;
    g_kern_e[(s * T_NO + tau) * HID_NO + h] = ae;
    g_kern_i[(s * T_NO + tau) * HID_NO + h] = ai;
}

// ---------------- K2: synapse pooling (thread-per-t, transposed smem staging) ----
// dynamic smem layout (floats): sCe [1024*8] | sCi [256*8] | sX [32*257]
#define SME_CE 0
#define SME_CI (1024 * 8)                // 8192
#define SME_X  (SME_CI + 256 * 8)        // 10240
#define SME_TOTAL (SME_X + 32 * 257)     // 18464 floats = 73856 B
#define XSTRIDE 257

__global__ void __launch_bounds__(256)
pool_kernel(const float* __restrict__ S_e, const float* __restrict__ S_i) {
    extern __shared__ float smem[];
    float* sCe = smem + SME_CE;
    float* sCi = smem + SME_CI;
    float* sX  = smem + SME_X;

    int tid = threadIdx.x;
    int b = blockIdx.y;
    int t0 = blockIdx.x * 256;
    int t = t0 + tid;                 // this thread's output column
    bool tvalid = (t < T_LEN);

    // fill C tables (coalesced float4)
    for (int i = tid; i < 1024 * 8 / 4; i += 256)
        ((float4*)sCe)[i] = ((const float4*)g_CTe)[i];
    for (int i = tid; i < 256 * 8 / 4; i += 256)
        ((float4*)sCi)[i] = ((const float4*)g_CTi)[i];

    int g  = tid & 7;                 // float4 slot within 32-e chunk
    int tr = tid >> 3;                // base t-row for loads (0..31)
    int g4 = g * 4;

    float2 acc[4];
#pragma unroll
    for (int sp = 0; sp < 4; ++sp) acc[sp] = make_float2(0.f, 0.f);

    float4 v[8];

    // ================= E section: 32 chunks of 32 e =================
    {
        // prologue: load chunk 0 (S_e rows are 4000B -> 16B aligned, float4 OK)
        int e0 = g4;
#pragma unroll
        for (int k = 0; k < 8; ++k) {
            int trow = t0 + tr + 32 * k;
            v[k] = (trow < T_LEN && e0 + 3 < E_NUM)
                   ? *(const float4*)(S_e + (size_t)(b * T_LEN + trow) * E_NUM + e0)
                   : make_float4(0.f, 0.f, 0.f, 0.f);
        }
        __syncthreads();   // C fill done

        for (int c = 0; c < 32; ++c) {
            // store chunk c (transposed, conflict-free)
#pragma unroll
            for (int k = 0; k < 8; ++k) {
                int tcol = tr + 32 * k;
                sX[(g4 + 0) * XSTRIDE + tcol] = v[k].x;
                sX[(g4 + 1) * XSTRIDE + tcol] = v[k].y;
                sX[(g4 + 2) * XSTRIDE + tcol] = v[k].z;
                sX[(g4 + 3) * XSTRIDE + tcol] = v[k].w;
            }
            __syncthreads();
            // prefetch chunk c+1
            if (c + 1 < 32) {
                int e = (c + 1) * 32 + g4;
#pragma unroll
                for (int k = 0; k < 8; ++k) {
                    int trow = t0 + tr + 32 * k;
                    v[k] = (trow < T_LEN && e + 3 < E_NUM)
                           ? *(const float4*)(S_e + (size_t)(b * T_LEN + trow) * E_NUM + e)
                           : make_float4(0.f, 0.f, 0.f, 0.f);
                }
            }
            // compute chunk c
            const float* Crow = sCe + c * 32 * 8;
#pragma unroll
            for (int el = 0; el < 32; ++el) {
                float x = sX[el * XSTRIDE + tid];
                float4 cA = *(const float4*)(Crow + el * 8);
                float4 cB = *(const float4*)(Crow + el * 8 + 4);
                float2 vv = make_float2(x, x);
                acc[0] = ffma2(make_float2(cA.x, cA.y), vv, acc[0]);
                acc[1] = ffma2(make_float2(cA.z, cA.w), vv, acc[1]);
                acc[2] = ffma2(make_float2(cB.x, cB.y), vv, acc[2]);
                acc[3] = ffma2(make_float2(cB.z, cB.w), vv, acc[3]);
            }
            __syncthreads();
        }
        if (tvalid) {
            float* dst = &g_syn_e[(b * SUB_NO) * T_LEN + t];
#pragma unroll
            for (int sp = 0; sp < 4; ++sp) {
                dst[(2 * sp) * T_LEN]     = acc[sp].x;
                dst[(2 * sp + 1) * T_LEN] = acc[sp].y;
            }
        }
    }

    // ================= I section: 8 chunks of 32 e =================
    // S_i rows are 1000B (8-aligned, NOT 16-aligned) -> compose float4 from two float2.
    {
#pragma unroll
        for (int sp = 0; sp < 4; ++sp) acc[sp] = make_float2(0.f, 0.f);

        // prologue: chunk 0 fully inside (g4+3 <= 31 < 250)
#pragma unroll
        for (int k = 0; k < 8; ++k) {
            int trow = t0 + tr + 32 * k;
            if (trow < T_LEN) {
                const float* row = S_i + (size_t)(b * T_LEN + trow) * I_NUM + g4;
                float2 lo = *(const float2*)(row);
                float2 hi = *(const float2*)(row + 2);
                v[k] = make_float4(lo.x, lo.y, hi.x, hi.y);
            } else {
                v[k] = make_float4(0.f, 0.f, 0.f, 0.f);
            }
        }

        for (int c = 0; c < 8; ++c) {
#pragma unroll
            for (int k = 0; k < 8; ++k) {
                int tcol = tr + 32 * k;
                sX[(g4 + 0) * XSTRIDE + tcol] = v[k].x;
                sX[(g4 + 1) * XSTRIDE + tcol] = v[k].y;
                sX[(g4 + 2) * XSTRIDE + tcol] = v[k].z;
                sX[(g4 + 3) * XSTRIDE + tcol] = v[k].w;
            }
            __syncthreads();
            if (c + 1 < 8) {
                int e = (c + 1) * 32 + g4;
#pragma unroll
                for (int k = 0; k < 8; ++k) {
                    int trow = t0 + tr + 32 * k;
                    if (trow < T_LEN && e + 3 < I_NUM) {
                        const float* row = S_i + (size_t)(b * T_LEN + trow) * I_NUM + e;
                        float2 lo = *(const float2*)(row);
                        float2 hi = *(const float2*)(row + 2);
                        v[k] = make_float4(lo.x, lo.y, hi.x, hi.y);
                    } else {
                        float a0 = 0.f, a1 = 0.f, a2 = 0.f, a3 = 0.f;
                        if (trow < T_LEN) {
                            const float* row = S_i + (size_t)(b * T_LEN + trow) * I_NUM;
                            if (e + 0 < I_NUM) a0 = row[e + 0];
                            if (e + 1 < I_NUM) a1 = row[e + 1];
                            if (e + 2 < I_NUM) a2 = row[e + 2];
                            if (e + 3 < I_NUM) a3 = row[e + 3];
                        }
                        v[k] = make_float4(a0, a1, a2, a3);
                    }
                }
            }
            const float* Crow = sCi + c * 32 * 8;
#pragma unroll
            for (int el = 0; el < 32; ++el) {
                float x = sX[el * XSTRIDE + tid];
                float4 cA = *(const float4*)(Crow + el * 8);
                float4 cB = *(const float4*)(Crow + el * 8 + 4);
                float2 vv = make_float2(x, x);
                acc[0] = ffma2(make_float2(cA.x, cA.y), vv, acc[0]);
                acc[1] = ffma2(make_float2(cA.z, cA.w), vv, acc[1]);
                acc[2] = ffma2(make_float2(cB.x, cB.y), vv, acc[2]);
                acc[3] = ffma2(make_float2(cB.z, cB.w), vv, acc[3]);
            }
            __syncthreads();
        }
        if (tvalid) {
            float* dst = &g_syn_i[(b * SUB_NO) * T_LEN + t];
#pragma unroll
            for (int sp = 0; sp < 4; ++sp) {
                dst[(2 * sp) * T_LEN]     = acc[sp].x;
                dst[(2 * sp + 1) * T_LEN] = acc[sp].y;
            }
        }
    }
}

// ---------------- K3: causal conv + tanh + readout (fma-bound) ----------------
#define CROWS 3
#define TC (256 * CROWS)      // 768
#define XW (TC + T_NO)        // 968

__global__ void __launch_bounds__(256)
conv_kernel(const float* __restrict__ W2,
            const float* __restrict__ b1,
            float* __restrict__ out) {
    __shared__ __align__(16) float4 sKe[T_NO * 4];   // [tau][4 float4] = 16 h
    __shared__ __align__(16) float4 sKi[T_NO * 4];
    __shared__ float sXe[XW], sXi[XW];
    __shared__ float sEw2[HID_NO], sB1[HID_NO];

    int tid = threadIdx.x;
    int bs = blockIdx.y;
    int b = bs >> 3, s = bs & 7;
    int t0 = blockIdx.x * TC;

    const float4* ge = (const float4*)g_kern_e + s * (T_NO * 4);
    const float4* gi = (const float4*)g_kern_i + s * (T_NO * 4);
    for (int idx = tid; idx < T_NO * 4; idx += 256) {
        sKe[idx] = ge[idx];
        sKi[idx] = gi[idx];
    }
    for (int idx = tid; idx < XW; idx += 256) {
        int g = t0 - (T_NO - 1) + idx;
        bool ok = (g >= 0) && (g < T_LEN);
        sXe[idx] = ok ? g_syn_e[(b * SUB_NO + s) * T_LEN + g] : 0.0f;
        sXi[idx] = ok ? g_syn_i[(b * SUB_NO + s) * T_LEN + g] : 0.0f;
    }
    if (tid < HID_NO) {
        sEw2[tid] = expf(W2[s * HID_NO + tid]);
        sB1[tid]  = b1[s * HID_NO + tid];
    }
    __syncthreads();

    float2 acc[CROWS][8];
#pragma unroll
    for (int r = 0; r < CROWS; ++r)
#pragma unroll
        for (int hp = 0; hp < 8; ++hp) acc[r][hp] = make_float2(0.f, 0.f);

    int o0 = tid + (T_NO - 1);

#pragma unroll 2
    for (int tau = 0; tau < T_NO; ++tau) {
        float4 ke[4], ki[4];
#pragma unroll
        for (int q = 0; q < 4; ++q) { ke[q] = sKe[tau * 4 + q]; ki[q] = sKi[tau * 4 + q]; }
        float xe[CROWS], xi[CROWS];
#pragma unroll
        for (int r = 0; r < CROWS; ++r) {
            xe[r] = sXe[o0 + r * 256 - tau];
            xi[r] = sXi[o0 + r * 256 - tau];
        }
#pragma unroll
        for (int r = 0; r < CROWS; ++r) {
            float2 ve = make_float2(xe[r], xe[r]);
            float2 vi = make_float2(xi[r], xi[r]);
#pragma unroll
            for (int q = 0; q < 4; ++q) {
                acc[r][2*q]   = ffma2(make_float2(ke[q].x, ke[q].y), ve, acc[r][2*q]);
                acc[r][2*q+1] = ffma2(make_float2(ke[q].z, ke[q].w), ve, acc[r][2*q+1]);
                acc[r][2*q]   = ffma2(make_float2(ki[q].x, ki[q].y), vi, acc[r][2*q]);
                acc[r][2*q+1] = ffma2(make_float2(ki[q].z, ki[q].w), vi, acc[r][2*q+1]);
            }
        }
    }

    // epilogue: tanh + positive readout -> sub_out[b, t, s]
#pragma unroll
    for (int r = 0; r < CROWS; ++r) {
        int t = t0 + tid + r * 256;
        if (t < T_LEN) {
            float so = 0.0f;
#pragma unroll
            for (int hp = 0; hp < 8; ++hp) {
                so = fmaf(sEw2[2*hp],   tanh_fast(acc[r][hp].x + sB1[2*hp]),   so);
                so = fmaf(sEw2[2*hp+1], tanh_fast(acc[r][hp].y + sB1[2*hp+1]), so);
            }
            out[SUBOUT_OFF + (size_t)(b * T_LEN + t) * SUB_NO + s] = so;
        }
    }
}

// ---------------- K4: final = sum_s sub_out + V_o ----------------
__global__ void final_kernel(const float* __restrict__ V_o, float* __restrict__ out) {
    int idx = blockIdx.x * blockDim.x + threadIdx.x;
    if (idx >= B_NO * T_LEN) return;
    const float4* p = (const float4*)&out[SUBOUT_OFF + (size_t)idx * SUB_NO];
    float4 a = p[0], c = p[1];
    out[FINAL_OFF + idx] = V_o[0] + ((a.x + a.y) + (a.z + a.w)) + ((c.x + c.y) + (c.z + c.w));
}

// ---------------- launch ----------------
extern "C" void kernel_launch(void* const* d_in, const int* in_sizes, int n_in,
                              void* d_out, int out_size) {
    (void)in_sizes; (void)n_in; (void)out_size;
    const float* S_e   = (const float*)d_in[0];
    const float* S_i   = (const float*)d_in[1];
    const float* Es    = (const float*)d_in[2];
    const float* Is    = (const float*)d_in[3];
    const float* W_e   = (const float*)d_in[4];
    const float* W_i   = (const float*)d_in[5];
    const float* W2    = (const float*)d_in[6];
    const float* b1    = (const float*)d_in[7];
    const float* Cer   = (const float*)d_in[8];
    const float* Cir   = (const float*)d_in[9];
    const float* V_o   = (const float*)d_in[10];
    float* out = (float*)d_out;

    softmax_kernel<<<(E_NUM + I_NUM + 30 + 255) / 256, 256>>>(Cer, Cir, Es, Is, out);
    kern_kernel<<<T_NO, 128>>>(W_e, W_i);

    int smem_bytes = SME_TOTAL * (int)sizeof(float);   // 73856
    cudaFuncSetAttribute(pool_kernel, cudaFuncAttributeMaxDynamicSharedMemorySize, smem_bytes);
    dim3 pg((T_LEN + 255) / 256, B_NO);                // 40 x 8 = 320 blocks
    pool_kernel<<<pg, 256, smem_bytes>>>(S_e, S_i);

    dim3 cg((T_LEN + TC - 1) / TC, B_NO * SUB_NO);     // 14 x 64
    conv_kernel<<<cg, 256>>>(W2, b1, out);

    final_kernel<<<(B_NO * T_LEN + 255) / 256, 256>>>(V_o, out);
}